// round 2
// baseline (speedup 1.0000x reference)
#include <cuda_runtime.h>

// SMFNet: chord-masked iterative mixing, fully fused, occupancy-oriented shape.
// B=2, N=8192, D=64, DV=64, M=3.
// mask = diag + (i,(i+1)%N)  =>  per-iter: V'[i] = a_i V[i] + c_i V[i+1]
// Unrolled over M=3:
//   V3[i] = (w0 X[i] + w1 X[i+1] + w2 X[i+2] + w3 X[i+3]) @ Wg + (sum w) * bg
//   w0 = A3 A2_i A1_i
//   w1 = A3 (A2_i C1_i + C2_i A1_{i+1}) + C3 A2_{i+1} A1_{i+1}
//   w2 = A3 C2_i C1_{i+1} + C3 (A2_{i+1} C1_{i+1} + C2_{i+1} A1_{i+2})
//   w3 = C3 C2_{i+1} C1_{i+2}
// Am_j = X[j]·Wf[m][:,j] + bf[m][j],  Cm_j = X[j]·Wf[m][:,j+1] + bf[m][j+1]

#define Bc   2
#define Nc   8192
#define Dc   64
#define TROWS 32          // output rows per CTA -> 512 CTAs total
#define XROWS 35          // X rows staged (TROWS+3)
#define XPAD  68          // float4-aligned row stride for Xs
#define XWPAD 65          // conflict-free scalar stride for Xws (65 mod 32 == 1)
#define ACR   36          // A/C array stride (need rows 0..33)
#define NTHREADS 256

// dynamic smem layout (floats)
#define OFF_XS    0                        // XROWS * XPAD
#define OFF_WGS   (OFF_XS  + XROWS*XPAD)   // 64*64
#define OFF_XWS   (OFF_WGS + 64*64)        // TROWS * XWPAD
#define OFF_AS    (OFF_XWS + TROWS*XWPAD)  // 3*ACR
#define OFF_CS    (OFF_AS  + 3*ACR)        // 3*ACR
#define OFF_WC    (OFF_CS  + 3*ACR)        // TROWS*4
#define OFF_WSUM  (OFF_WC  + TROWS*4)      // TROWS
#define OFF_BGS   (OFF_WSUM + TROWS)       // 64
#define SMEM_FLOATS (OFF_BGS + 64)
#define SMEM_BYTES (SMEM_FLOATS * 4)

__global__ __launch_bounds__(NTHREADS, 4)
void smf_fused_kernel(const float* __restrict__ X,
                      const float* __restrict__ Wg,
                      const float* __restrict__ bg,
                      const float* __restrict__ Wf,
                      const float* __restrict__ bf,
                      float* __restrict__ out)
{
    extern __shared__ float sm[];
    float* Xs   = sm + OFF_XS;
    float* Wgs  = sm + OFF_WGS;
    float* Xws  = sm + OFF_XWS;
    float* As   = sm + OFF_AS;
    float* Cs   = sm + OFF_CS;
    float* Wc   = sm + OFF_WC;
    float* Wsum = sm + OFF_WSUM;
    float* bgs  = sm + OFF_BGS;

    const int t  = threadIdx.x;
    const int b  = blockIdx.y;
    const int r0 = blockIdx.x * TROWS;
    const float* Xb = X + (size_t)b * Nc * Dc;

    // ---- Phase 1: stage Wg, bg, X rows [r0, r0+35) (wrap mod N), float4 ----
    {
        const float4* Wg4 = reinterpret_cast<const float4*>(Wg);
        #pragma unroll
        for (int idx = t; idx < 64 * 16; idx += NTHREADS) {
            float4 v = Wg4[idx];
            *reinterpret_cast<float4*>(&Wgs[idx * 4]) = v;
        }
        if (t < 64) bgs[t] = bg[t];
        const float4* Xb4 = reinterpret_cast<const float4*>(Xb);
        for (int idx = t; idx < XROWS * 16; idx += NTHREADS) {
            int j = idx >> 4, q = idx & 15;
            int gi = (r0 + j) & (Nc - 1);
            float4 v = Xb4[gi * 16 + q];
            *reinterpret_cast<float4*>(&Xs[j * XPAD + q * 4]) = v;
        }
    }
    __syncthreads();

    // ---- Phase 2: a/c scalars, thread per (row j, layer m): 34*3 = 102 tasks ----
    if (t < 34 * 3) {
        const int j  = t / 3;
        const int m  = t - 3 * j;
        const int gi  = (r0 + j) & (Nc - 1);
        const int gi1 = (gi + 1) & (Nc - 1);
        const float* Wm = Wf + (size_t)m * Dc * Nc;
        float a = 0.f, c = 0.f;
        #pragma unroll 8
        for (int d = 0; d < Dc; d++) {
            float xv = Xs[j * XPAD + d];
            const float* p = Wm + (size_t)d * Nc;
            a += xv * __ldg(p + gi);
            c += xv * __ldg(p + gi1);
        }
        As[m * ACR + j] = a + bf[m * Nc + gi];
        Cs[m * ACR + j] = c + bf[m * Nc + gi1];
    }
    __syncthreads();

    // ---- Phase 3: 4-tap weights per output row ----
    if (t < TROWS) {
        const int j = t;
        float A1i  = As[0 * ACR + j], A1i1 = As[0 * ACR + j + 1], A1i2 = As[0 * ACR + j + 2];
        float C1i  = Cs[0 * ACR + j], C1i1 = Cs[0 * ACR + j + 1], C1i2 = Cs[0 * ACR + j + 2];
        float A2i  = As[1 * ACR + j], A2i1 = As[1 * ACR + j + 1];
        float C2i  = Cs[1 * ACR + j], C2i1 = Cs[1 * ACR + j + 1];
        float A3   = As[2 * ACR + j], C3   = Cs[2 * ACR + j];
        float w0 = A3 * A2i * A1i;
        float w1 = A3 * (A2i * C1i + C2i * A1i1) + C3 * A2i1 * A1i1;
        float w2 = A3 * C2i * C1i1 + C3 * (A2i1 * C1i1 + C2i1 * A1i2);
        float w3 = C3 * C2i1 * C1i2;
        Wc[j * 4 + 0] = w0; Wc[j * 4 + 1] = w1;
        Wc[j * 4 + 2] = w2; Wc[j * 4 + 3] = w3;
        Wsum[j] = w0 + w1 + w2 + w3;
    }
    __syncthreads();

    // ---- Phase 4: combined rows Xw[j] = sum_k w_k X[j+k] ----
    #pragma unroll
    for (int idx = t; idx < TROWS * 64; idx += NTHREADS) {
        int j = idx >> 6, d = idx & 63;
        float v = Wc[j * 4 + 0] * Xs[ j      * XPAD + d]
                + Wc[j * 4 + 1] * Xs[(j + 1) * XPAD + d]
                + Wc[j * 4 + 2] * Xs[(j + 2) * XPAD + d]
                + Wc[j * 4 + 3] * Xs[(j + 3) * XPAD + d];
        Xws[j * XWPAD + d] = v;
    }
    __syncthreads();

    // ---- Phase 5: matvec Xw @ Wg + wsum*bg ----
    // thread tile: rows {rc, rc+16}, cols [e0, e0+4); scattered rows keep
    // xv LDS conflict-free with XWPAD=65.
    {
        const int rc = t & 15;
        const int e0 = (t >> 4) * 4;
        float acc[2][4];
        #pragma unroll
        for (int r = 0; r < 2; r++)
            #pragma unroll
            for (int c = 0; c < 4; c++) acc[r][c] = 0.f;

        #pragma unroll 8
        for (int d = 0; d < Dc; d++) {
            float4 wv = *reinterpret_cast<const float4*>(&Wgs[d * 64 + e0]);
            float x0 = Xws[ rc        * XWPAD + d];
            float x1 = Xws[(rc + 16)  * XWPAD + d];
            acc[0][0] += x0 * wv.x;  acc[0][1] += x0 * wv.y;
            acc[0][2] += x0 * wv.z;  acc[0][3] += x0 * wv.w;
            acc[1][0] += x1 * wv.x;  acc[1][1] += x1 * wv.y;
            acc[1][2] += x1 * wv.z;  acc[1][3] += x1 * wv.w;
        }
        #pragma unroll
        for (int r = 0; r < 2; r++) {
            const int j  = rc + 16 * r;
            const int gi = (r0 + j) & (Nc - 1);
            const float ws = Wsum[j];
            float4 o;
            o.x = acc[r][0] + ws * bgs[e0 + 0];
            o.y = acc[r][1] + ws * bgs[e0 + 1];
            o.z = acc[r][2] + ws * bgs[e0 + 2];
            o.w = acc[r][3] + ws * bgs[e0 + 3];
            *reinterpret_cast<float4*>(&out[((size_t)b * Nc + gi) * 64 + e0]) = o;
        }
    }
}

extern "C" void kernel_launch(void* const* d_in, const int* in_sizes, int n_in,
                              void* d_out, int out_size)
{
    const float* X  = (const float*)d_in[0];   // (2, 8192, 64)
    const float* Wg = (const float*)d_in[1];   // (64, 64)
    const float* bg = (const float*)d_in[2];   // (64,)
    const float* Wf = (const float*)d_in[3];   // (3, 64, 8192)
    const float* bf = (const float*)d_in[4];   // (3, 8192)
    float* out = (float*)d_out;                // (2, 8192, 64)

    cudaFuncSetAttribute(smf_fused_kernel,
                         cudaFuncAttributeMaxDynamicSharedMemorySize, SMEM_BYTES);

    dim3 grid(Nc / TROWS, Bc);
    smf_fused_kernel<<<grid, NTHREADS, SMEM_BYTES>>>(X, Wg, bg, Wf, bf, out);
}